// round 11
// baseline (speedup 1.0000x reference)
#include <cuda_runtime.h>
#include <cstdint>

#define Bz   128
#define Nn   196
#define DIMc 384
#define Kk   16
#define Hh   6
#define DR   96
#define TMX  28   // mixer m-tile width; 7*28 == 196
#define CH   28   // mixer n-chunk; 7*28 == 196
#define NCH  7

// Scratch (device globals — allocation-free)
__device__ __align__(16) float g_wbt[(size_t)Nn * Nn * Kk];      // [n][m][k]
__device__ __align__(16) float g_mix[(size_t)Bz * Nn * Hh * Kk]; // [b][n][h][k]

typedef unsigned long long ull;

__device__ __forceinline__ ull fma2(ull a, ull b, ull c) {
    ull d;
    asm("fma.rn.f32x2 %0, %1, %2, %3;" : "=l"(d) : "l"(a), "l"(b), "l"(c));
    return d;
}
__device__ __forceinline__ ull pack2(float lo, float hi) {
    ull d;
    asm("mov.b64 %0, {%1, %2};" : "=l"(d) : "r"(__float_as_uint(lo)), "r"(__float_as_uint(hi)));
    return d;
}
__device__ __forceinline__ float2 unpack2(ull v) {
    unsigned lo, hi;
    asm("mov.b64 {%0, %1}, %2;" : "=r"(lo), "=r"(hi) : "l"(v));
    return make_float2(__uint_as_float(lo), __uint_as_float(hi));
}

// ---------------------------------------------------------------------------
// Kernel 1: weight_bank [k][n][m] -> g_wbt [n][m][k]  (k contiguous)
// ---------------------------------------------------------------------------
extern "C" __global__ void transpose_wb_kernel(const float* __restrict__ wb) {
    int t = blockIdx.x * 256 + threadIdx.x;
    if (t >= Nn * Nn) return;
    int n = t / Nn, m = t % Nn;
    float v[Kk];
#pragma unroll
    for (int k = 0; k < Kk; ++k)
        v[k] = wb[((size_t)k * Nn + n) * Nn + m];   // coalesced over m
    float4* dst = (float4*)&g_wbt[(size_t)t * Kk];
    dst[0] = make_float4(v[0],  v[1],  v[2],  v[3]);
    dst[1] = make_float4(v[4],  v[5],  v[6],  v[7]);
    dst[2] = make_float4(v[8],  v[9],  v[10], v[11]);
    dst[3] = make_float4(v[12], v[13], v[14], v[15]);
}

// ---------------------------------------------------------------------------
// Kernel 2: adapter (best measured). UNCHANGED from R10.
// 64 rows/block, 192 threads (12 colgroups x 16 rowgroups).
// ---------------------------------------------------------------------------
#define AD_SMEM_FLOATS (9216 + 96*68)

extern "C" __global__ void __launch_bounds__(192)
adapter_kernel(const float* __restrict__ x,
               const float* __restrict__ W1, const float* __restrict__ b1,
               const float* __restrict__ W2, const float* __restrict__ b2) {
    extern __shared__ float sm[];
    float* Ws = sm;            // 9216 floats (96x96)
    float* Xs = sm + 9216;     // 96 x 68 (padded), reused as Hs

    const int t   = threadIdx.x;
    const int tc  = t % 12;           // col group
    const int rg  = t / 12;           // row group
    const int j0  = tc * 8;
    const int r0  = rg * 4;
    const int row0 = blockIdx.x * 64; // 392 blocks * 64 = 25088 rows

    ull acc[4][4];
#pragma unroll
    for (int r = 0; r < 4; ++r)
#pragma unroll
        for (int p = 0; p < 4; ++p) acc[r][p] = 0ull;

    // ---- phase 1: hid = x @ W1 over 4 i-tiles of 96 ----
    for (int it = 0; it < 4; ++it) {
        __syncthreads();
        for (int idx = t; idx < 9216; idx += 192)
            Ws[idx] = W1[(size_t)it * 96 * 96 + idx];
        for (int idx = t; idx < 6144; idx += 192) {
            int il = idx % 96, r = idx / 96;
            Xs[il * 68 + r] = x[(size_t)(row0 + r) * DIMc + it * 96 + il];
        }
        __syncthreads();
#pragma unroll 4
        for (int il = 0; il < 96; ++il) {
            const ulonglong2 wA = *(const ulonglong2*)&Ws[il * 96 + j0];
            const ulonglong2 wB = *(const ulonglong2*)&Ws[il * 96 + j0 + 4];
            const float4 xv = *(const float4*)&Xs[il * 68 + r0];
            ull xd0 = pack2(xv.x, xv.x), xd1 = pack2(xv.y, xv.y);
            ull xd2 = pack2(xv.z, xv.z), xd3 = pack2(xv.w, xv.w);
            acc[0][0] = fma2(wA.x, xd0, acc[0][0]);
            acc[0][1] = fma2(wA.y, xd0, acc[0][1]);
            acc[0][2] = fma2(wB.x, xd0, acc[0][2]);
            acc[0][3] = fma2(wB.y, xd0, acc[0][3]);
            acc[1][0] = fma2(wA.x, xd1, acc[1][0]);
            acc[1][1] = fma2(wA.y, xd1, acc[1][1]);
            acc[1][2] = fma2(wB.x, xd1, acc[1][2]);
            acc[1][3] = fma2(wB.y, xd1, acc[1][3]);
            acc[2][0] = fma2(wA.x, xd2, acc[2][0]);
            acc[2][1] = fma2(wA.y, xd2, acc[2][1]);
            acc[2][2] = fma2(wB.x, xd2, acc[2][2]);
            acc[2][3] = fma2(wB.y, xd2, acc[2][3]);
            acc[3][0] = fma2(wA.x, xd3, acc[3][0]);
            acc[3][1] = fma2(wA.y, xd3, acc[3][1]);
            acc[3][2] = fma2(wB.x, xd3, acc[3][2]);
            acc[3][3] = fma2(wB.y, xd3, acc[3][3]);
        }
    }
    __syncthreads();

    // ---- GELU(exact) + write Hs (transposed) ; load W2 into Ws ----
    for (int idx = t; idx < 9216; idx += 192) Ws[idx] = W2[idx];
    float* Hs = Xs;
#pragma unroll
    for (int r = 0; r < 4; ++r)
#pragma unroll
        for (int p = 0; p < 4; ++p) {
            float2 v = unpack2(acc[r][p]);
            int j = j0 + 2 * p;
            float a0 = v.x + b1[j];
            float a1 = v.y + b1[j + 1];
            a0 = 0.5f * a0 * (1.0f + erff(a0 * 0.7071067811865476f));
            a1 = 0.5f * a1 * (1.0f + erff(a1 * 0.7071067811865476f));
            Hs[(size_t)j       * 68 + r0 + r] = a0;
            Hs[(size_t)(j + 1) * 68 + r0 + r] = a1;
        }
    __syncthreads();

    // ---- phase 2: mix = hid @ W2 ----
    ull acc2[4][4];
#pragma unroll
    for (int r = 0; r < 4; ++r)
#pragma unroll
        for (int p = 0; p < 4; ++p) acc2[r][p] = 0ull;
#pragma unroll 4
    for (int i = 0; i < 96; ++i) {
        const ulonglong2 wA = *(const ulonglong2*)&Ws[i * 96 + j0];
        const ulonglong2 wB = *(const ulonglong2*)&Ws[i * 96 + j0 + 4];
        const float4 hv = *(const float4*)&Hs[i * 68 + r0];
        ull xd0 = pack2(hv.x, hv.x), xd1 = pack2(hv.y, hv.y);
        ull xd2 = pack2(hv.z, hv.z), xd3 = pack2(hv.w, hv.w);
        acc2[0][0] = fma2(wA.x, xd0, acc2[0][0]);
        acc2[0][1] = fma2(wA.y, xd0, acc2[0][1]);
        acc2[0][2] = fma2(wB.x, xd0, acc2[0][2]);
        acc2[0][3] = fma2(wB.y, xd0, acc2[0][3]);
        acc2[1][0] = fma2(wA.x, xd1, acc2[1][0]);
        acc2[1][1] = fma2(wA.y, xd1, acc2[1][1]);
        acc2[1][2] = fma2(wB.x, xd1, acc2[1][2]);
        acc2[1][3] = fma2(wB.y, xd1, acc2[1][3]);
        acc2[2][0] = fma2(wA.x, xd2, acc2[2][0]);
        acc2[2][1] = fma2(wA.y, xd2, acc2[2][1]);
        acc2[2][2] = fma2(wB.x, xd2, acc2[2][2]);
        acc2[2][3] = fma2(wB.y, xd2, acc2[2][3]);
        acc2[3][0] = fma2(wA.x, xd3, acc2[3][0]);
        acc2[3][1] = fma2(wA.y, xd3, acc2[3][1]);
        acc2[3][2] = fma2(wB.x, xd3, acc2[3][2]);
        acc2[3][3] = fma2(wB.y, xd3, acc2[3][3]);
    }
    __syncthreads();

    // ---- + b2, stage to Ms, softmax over k ----
    float* Ms = Ws;
#pragma unroll
    for (int r = 0; r < 4; ++r)
#pragma unroll
        for (int p = 0; p < 4; ++p) {
            float2 v = unpack2(acc2[r][p]);
            int j = j0 + 2 * p;
            Ms[(r0 + r) * 96 + j]     = v.x + b2[j];
            Ms[(r0 + r) * 96 + j + 1] = v.y + b2[j + 1];
        }
    __syncthreads();

    for (int g = t; g < 384; g += 192) {
        int r = g / 6, h = g % 6;
        float vals[Kk];
        float vmax = -1e30f;
#pragma unroll
        for (int k = 0; k < Kk; ++k) {
            vals[k] = Ms[r * 96 + k * Hh + h];
            vmax = fmaxf(vmax, vals[k]);
        }
        float s = 0.f;
#pragma unroll
        for (int k = 0; k < Kk; ++k) { vals[k] = __expf(vals[k] - vmax); s += vals[k]; }
        float inv = 1.0f / s;
        size_t base = ((size_t)(row0 + r) * Hh + h) * Kk;
#pragma unroll
        for (int k = 0; k < Kk; ++k) g_mix[base + k] = vals[k] * inv;
    }
}

// ---------------------------------------------------------------------------
// Kernel 3: fused mixer — EXACT v3 (R6) form: plain float4 ld/st staging,
// scalar dot-16 phase 1, f32x2 phase 2. cp.async removed (R10 suspect).
// Block = (m-tile of 28, batch b), 384 threads, 2 CTAs/SM.
// ---------------------------------------------------------------------------
#define MX_XS   10752
#define MX_MIX  2688
#define MX_WS   5376
#define MX_SMEM_FLOATS (MX_XS + MX_MIX + MX_WS)

extern "C" __global__ void __launch_bounds__(384, 2)
mixer_kernel(const float* __restrict__ x, float* __restrict__ out) {
    extern __shared__ float sm[];
    float* xs    = sm;                     // [nl][384]
    float* mix_s = sm + MX_XS;             // [nl][96]  ([h][k] inner)
    float* ws    = sm + MX_XS + MX_MIX;    // [nl][h][32] (m padded 28->32)

    const int t  = threadIdx.x;
    const int b  = blockIdx.y;
    const int mt = blockIdx.x;    // 0..6
    const int h  = t >> 6;

    ull acc[14];
#pragma unroll
    for (int q = 0; q < 14; ++q) acc[q] = 0ull;

    for (int c = 0; c < NCH; ++c) {
        const int n0 = c * CH;
        __syncthreads();
        // stage x chunk: 28*384 floats = 2688 float4, 7 per thread
        {
            const float4* src = (const float4*)(x + ((size_t)b * Nn + n0) * DIMc);
            float4* dst = (float4*)xs;
#pragma unroll
            for (int i = 0; i < 7; ++i) dst[t + i * 384] = src[t + i * 384];
        }
        // stage mix chunk: 28*96 floats = 672 float4
        {
            const float4* src = (const float4*)&g_mix[((size_t)b * Nn + n0) * 96];
            float4* dst = (float4*)mix_s;
            for (int idx = t; idx < 672; idx += 384) dst[idx] = src[idx];
        }
        __syncthreads();
        // phase 1: 784 (nl, ml) pairs over 384 threads
        for (int p = t; p < CH * TMX; p += 384) {
            int nl = p / TMX, ml = p - nl * TMX;
            int mg = mt * TMX + ml;
            const float4* wv = (const float4*)&g_wbt[((size_t)(n0 + nl) * Nn + mg) * Kk];
            float4 w0 = __ldg(wv + 0), w1 = __ldg(wv + 1);
            float4 w2 = __ldg(wv + 2), w3 = __ldg(wv + 3);
#pragma unroll
            for (int hh = 0; hh < Hh; ++hh) {
                const float4* mx = (const float4*)&mix_s[nl * 96 + hh * Kk];
                float4 m0 = mx[0], m1 = mx[1], m2 = mx[2], m3 = mx[3];
                float s = w0.x * m0.x;
                s = fmaf(w0.y, m0.y, s); s = fmaf(w0.z, m0.z, s); s = fmaf(w0.w, m0.w, s);
                s = fmaf(w1.x, m1.x, s); s = fmaf(w1.y, m1.y, s); s = fmaf(w1.z, m1.z, s); s = fmaf(w1.w, m1.w, s);
                s = fmaf(w2.x, m2.x, s); s = fmaf(w2.y, m2.y, s); s = fmaf(w2.z, m2.z, s); s = fmaf(w2.w, m2.w, s);
                s = fmaf(w3.x, m3.x, s); s = fmaf(w3.y, m3.y, s); s = fmaf(w3.z, m3.z, s); s = fmaf(w3.w, m3.w, s);
                ws[(nl * Hh + hh) * 32 + ml] = s;
            }
        }
        __syncthreads();
        // phase 2: all operands in smem; 14 f32x2 accumulators over 28 m
#pragma unroll 4
        for (int nl = 0; nl < CH; ++nl) {
            float xv = xs[nl * 384 + t];
            ull xx = pack2(xv, xv);
            const float* wr = &ws[(nl * Hh + h) * 32];
            ulonglong2 wA = *(const ulonglong2*)&wr[0];
            ulonglong2 wB = *(const ulonglong2*)&wr[4];
            ulonglong2 wC = *(const ulonglong2*)&wr[8];
            ulonglong2 wD = *(const ulonglong2*)&wr[12];
            ulonglong2 wE = *(const ulonglong2*)&wr[16];
            ulonglong2 wF = *(const ulonglong2*)&wr[20];
            ulonglong2 wG = *(const ulonglong2*)&wr[24];
            acc[0]  = fma2(wA.x, xx, acc[0]);
            acc[1]  = fma2(wA.y, xx, acc[1]);
            acc[2]  = fma2(wB.x, xx, acc[2]);
            acc[3]  = fma2(wB.y, xx, acc[3]);
            acc[4]  = fma2(wC.x, xx, acc[4]);
            acc[5]  = fma2(wC.y, xx, acc[5]);
            acc[6]  = fma2(wD.x, xx, acc[6]);
            acc[7]  = fma2(wD.y, xx, acc[7]);
            acc[8]  = fma2(wE.x, xx, acc[8]);
            acc[9]  = fma2(wE.y, xx, acc[9]);
            acc[10] = fma2(wF.x, xx, acc[10]);
            acc[11] = fma2(wF.y, xx, acc[11]);
            acc[12] = fma2(wG.x, xx, acc[12]);
            acc[13] = fma2(wG.y, xx, acc[13]);
        }
    }

    float* ob = out + ((size_t)b * Nn + mt * TMX) * DIMc + t;
#pragma unroll
    for (int q = 0; q < 14; ++q) {
        float2 v = unpack2(acc[q]);
        ob[(size_t)(2 * q)     * DIMc] = v.x;
        ob[(size_t)(2 * q + 1) * DIMc] = v.y;
    }
}

// ---------------------------------------------------------------------------
extern "C" void kernel_launch(void* const* d_in, const int* in_sizes, int n_in,
                              void* d_out, int out_size) {
    const float* x  = (const float*)d_in[0];
    const float* W1 = (const float*)d_in[1];
    const float* b1 = (const float*)d_in[2];
    const float* W2 = (const float*)d_in[3];
    const float* b2 = (const float*)d_in[4];
    const float* wb = (const float*)d_in[5];
    float* out = (float*)d_out;

    cudaFuncSetAttribute((const void*)adapter_kernel,
                         cudaFuncAttributeMaxDynamicSharedMemorySize,
                         AD_SMEM_FLOATS * 4);
    cudaFuncSetAttribute((const void*)mixer_kernel,
                         cudaFuncAttributeMaxDynamicSharedMemorySize,
                         MX_SMEM_FLOATS * 4);

    transpose_wb_kernel<<<(Nn * Nn + 255) / 256, 256>>>(wb);
    adapter_kernel<<<392, 192, AD_SMEM_FLOATS * 4>>>(x, W1, b1, W2, b2);
    mixer_kernel<<<dim3(NCH, Bz), 384, MX_SMEM_FLOATS * 4>>>(x, out);
}

// round 12
// speedup vs baseline: 1.2370x; 1.2370x over previous
#include <cuda_runtime.h>
#include <cstdint>

#define Bz   128
#define Nn   196
#define DIMc 384
#define Kk   16
#define Hh   6
#define TMX  28   // mixer m-tile width per CTA; 7*28 == 196
#define CH   28   // mixer n-chunk; 7*28 == 196
#define NCH  7

// Scratch (device globals — allocation-free)
__device__ __align__(16) float g_wbt[(size_t)Nn * Nn * Kk];      // [n][m][k]
__device__ __align__(16) float g_mix[(size_t)Bz * Nn * Hh * Kk]; // [b][n][h][k]

typedef unsigned long long ull;

__device__ __forceinline__ ull fma2(ull a, ull b, ull c) {
    ull d;
    asm("fma.rn.f32x2 %0, %1, %2, %3;" : "=l"(d) : "l"(a), "l"(b), "l"(c));
    return d;
}
__device__ __forceinline__ ull pack2(float lo, float hi) {
    ull d;
    asm("mov.b64 %0, {%1, %2};" : "=l"(d) : "r"(__float_as_uint(lo)), "r"(__float_as_uint(hi)));
    return d;
}
__device__ __forceinline__ float2 unpack2(ull v) {
    unsigned lo, hi;
    asm("mov.b64 {%0, %1}, %2;" : "=r"(lo), "=r"(hi) : "l"(v));
    return make_float2(__uint_as_float(lo), __uint_as_float(hi));
}
__device__ __forceinline__ uint32_t tf32r(float f) {
    uint32_t u;
    asm("cvt.rna.tf32.f32 %0, %1;" : "=r"(u) : "f"(f));
    return u;
}
__device__ __forceinline__ void mma_tf32(float* c, uint32_t a0, uint32_t a1,
                                         uint32_t a2, uint32_t a3,
                                         uint32_t b0, uint32_t b1) {
    asm volatile(
        "mma.sync.aligned.m16n8k8.row.col.f32.tf32.tf32.f32 "
        "{%0,%1,%2,%3}, {%4,%5,%6,%7}, {%8,%9}, {%0,%1,%2,%3};"
        : "+f"(c[0]), "+f"(c[1]), "+f"(c[2]), "+f"(c[3])
        : "r"(a0), "r"(a1), "r"(a2), "r"(a3), "r"(b0), "r"(b1));
}

// ---------------------------------------------------------------------------
// Kernel 1: weight_bank [k][n][m] -> g_wbt [n][m][k]  (k contiguous)
// ---------------------------------------------------------------------------
extern "C" __global__ void transpose_wb_kernel(const float* __restrict__ wb) {
    int t = blockIdx.x * 256 + threadIdx.x;
    if (t >= Nn * Nn) return;
    int n = t / Nn, m = t % Nn;
    float v[Kk];
#pragma unroll
    for (int k = 0; k < Kk; ++k)
        v[k] = wb[((size_t)k * Nn + n) * Nn + m];   // coalesced over m
    float4* dst = (float4*)&g_wbt[(size_t)t * Kk];
    dst[0] = make_float4(v[0],  v[1],  v[2],  v[3]);
    dst[1] = make_float4(v[4],  v[5],  v[6],  v[7]);
    dst[2] = make_float4(v[8],  v[9],  v[10], v[11]);
    dst[3] = make_float4(v[12], v[13], v[14], v[15]);
}

// ---------------------------------------------------------------------------
// Kernel 2: adapter (best measured). UNCHANGED.
// ---------------------------------------------------------------------------
#define AD_SMEM_FLOATS (9216 + 96*68)

extern "C" __global__ void __launch_bounds__(192)
adapter_kernel(const float* __restrict__ x,
               const float* __restrict__ W1, const float* __restrict__ b1,
               const float* __restrict__ W2, const float* __restrict__ b2) {
    extern __shared__ float sm[];
    float* Ws = sm;            // 9216 floats (96x96)
    float* Xs = sm + 9216;     // 96 x 68 (padded), reused as Hs

    const int t   = threadIdx.x;
    const int tc  = t % 12;
    const int rg  = t / 12;
    const int j0  = tc * 8;
    const int r0  = rg * 4;
    const int row0 = blockIdx.x * 64;

    ull acc[4][4];
#pragma unroll
    for (int r = 0; r < 4; ++r)
#pragma unroll
        for (int p = 0; p < 4; ++p) acc[r][p] = 0ull;

    for (int it = 0; it < 4; ++it) {
        __syncthreads();
        for (int idx = t; idx < 9216; idx += 192)
            Ws[idx] = W1[(size_t)it * 96 * 96 + idx];
        for (int idx = t; idx < 6144; idx += 192) {
            int il = idx % 96, r = idx / 96;
            Xs[il * 68 + r] = x[(size_t)(row0 + r) * DIMc + it * 96 + il];
        }
        __syncthreads();
#pragma unroll 4
        for (int il = 0; il < 96; ++il) {
            const ulonglong2 wA = *(const ulonglong2*)&Ws[il * 96 + j0];
            const ulonglong2 wB = *(const ulonglong2*)&Ws[il * 96 + j0 + 4];
            const float4 xv = *(const float4*)&Xs[il * 68 + r0];
            ull xd0 = pack2(xv.x, xv.x), xd1 = pack2(xv.y, xv.y);
            ull xd2 = pack2(xv.z, xv.z), xd3 = pack2(xv.w, xv.w);
            acc[0][0] = fma2(wA.x, xd0, acc[0][0]);
            acc[0][1] = fma2(wA.y, xd0, acc[0][1]);
            acc[0][2] = fma2(wB.x, xd0, acc[0][2]);
            acc[0][3] = fma2(wB.y, xd0, acc[0][3]);
            acc[1][0] = fma2(wA.x, xd1, acc[1][0]);
            acc[1][1] = fma2(wA.y, xd1, acc[1][1]);
            acc[1][2] = fma2(wB.x, xd1, acc[1][2]);
            acc[1][3] = fma2(wB.y, xd1, acc[1][3]);
            acc[2][0] = fma2(wA.x, xd2, acc[2][0]);
            acc[2][1] = fma2(wA.y, xd2, acc[2][1]);
            acc[2][2] = fma2(wB.x, xd2, acc[2][2]);
            acc[2][3] = fma2(wB.y, xd2, acc[2][3]);
            acc[3][0] = fma2(wA.x, xd3, acc[3][0]);
            acc[3][1] = fma2(wA.y, xd3, acc[3][1]);
            acc[3][2] = fma2(wB.x, xd3, acc[3][2]);
            acc[3][3] = fma2(wB.y, xd3, acc[3][3]);
        }
    }
    __syncthreads();

    for (int idx = t; idx < 9216; idx += 192) Ws[idx] = W2[idx];
    float* Hs = Xs;
#pragma unroll
    for (int r = 0; r < 4; ++r)
#pragma unroll
        for (int p = 0; p < 4; ++p) {
            float2 v = unpack2(acc[r][p]);
            int j = j0 + 2 * p;
            float a0 = v.x + b1[j];
            float a1 = v.y + b1[j + 1];
            a0 = 0.5f * a0 * (1.0f + erff(a0 * 0.7071067811865476f));
            a1 = 0.5f * a1 * (1.0f + erff(a1 * 0.7071067811865476f));
            Hs[(size_t)j       * 68 + r0 + r] = a0;
            Hs[(size_t)(j + 1) * 68 + r0 + r] = a1;
        }
    __syncthreads();

    ull acc2[4][4];
#pragma unroll
    for (int r = 0; r < 4; ++r)
#pragma unroll
        for (int p = 0; p < 4; ++p) acc2[r][p] = 0ull;
#pragma unroll 4
    for (int i = 0; i < 96; ++i) {
        const ulonglong2 wA = *(const ulonglong2*)&Ws[i * 96 + j0];
        const ulonglong2 wB = *(const ulonglong2*)&Ws[i * 96 + j0 + 4];
        const float4 hv = *(const float4*)&Hs[i * 68 + r0];
        ull xd0 = pack2(hv.x, hv.x), xd1 = pack2(hv.y, hv.y);
        ull xd2 = pack2(hv.z, hv.z), xd3 = pack2(hv.w, hv.w);
        acc2[0][0] = fma2(wA.x, xd0, acc2[0][0]);
        acc2[0][1] = fma2(wA.y, xd0, acc2[0][1]);
        acc2[0][2] = fma2(wB.x, xd0, acc2[0][2]);
        acc2[0][3] = fma2(wB.y, xd0, acc2[0][3]);
        acc2[1][0] = fma2(wA.x, xd1, acc2[1][0]);
        acc2[1][1] = fma2(wA.y, xd1, acc2[1][1]);
        acc2[1][2] = fma2(wB.x, xd1, acc2[1][2]);
        acc2[1][3] = fma2(wB.y, xd1, acc2[1][3]);
        acc2[2][0] = fma2(wA.x, xd2, acc2[2][0]);
        acc2[2][1] = fma2(wA.y, xd2, acc2[2][1]);
        acc2[2][2] = fma2(wB.x, xd2, acc2[2][2]);
        acc2[2][3] = fma2(wB.y, xd2, acc2[2][3]);
        acc2[3][0] = fma2(wA.x, xd3, acc2[3][0]);
        acc2[3][1] = fma2(wA.y, xd3, acc2[3][1]);
        acc2[3][2] = fma2(wB.x, xd3, acc2[3][2]);
        acc2[3][3] = fma2(wB.y, xd3, acc2[3][3]);
    }
    __syncthreads();

    float* Ms = Ws;
#pragma unroll
    for (int r = 0; r < 4; ++r)
#pragma unroll
        for (int p = 0; p < 4; ++p) {
            float2 v = unpack2(acc2[r][p]);
            int j = j0 + 2 * p;
            Ms[(r0 + r) * 96 + j]     = v.x + b2[j];
            Ms[(r0 + r) * 96 + j + 1] = v.y + b2[j + 1];
        }
    __syncthreads();

    for (int g = t; g < 384; g += 192) {
        int r = g / 6, h = g % 6;
        float vals[Kk];
        float vmax = -1e30f;
#pragma unroll
        for (int k = 0; k < Kk; ++k) {
            vals[k] = Ms[r * 96 + k * Hh + h];
            vmax = fmaxf(vmax, vals[k]);
        }
        float s = 0.f;
#pragma unroll
        for (int k = 0; k < Kk; ++k) { vals[k] = __expf(vals[k] - vmax); s += vals[k]; }
        float inv = 1.0f / s;
        size_t base = ((size_t)(row0 + r) * Hh + h) * Kk;
#pragma unroll
        for (int k = 0; k < Kk; ++k) g_mix[base + k] = vals[k] * inv;
    }
}

// ---------------------------------------------------------------------------
// Kernel 3: mixer v6 — phase 2 on TENSOR pipe via mma.sync tf32 (m16n8k8).
// CTA = (b, mt of 28 m), 384 threads = 12 warps = 6 h x 2 mtiles(16).
// Per chunk (28 n, padded to 32 = 4 ktiles of 8):
//   stage xs[32][392] (x rounded to tf32; rows 28-31 zero)
//   phase1 (scalar fp32): ws[h][32m][36n] = dot16(mix, wbt), tf32-rounded
//   phase2: warp (h=w>>1, mt=w&1): acc[8nt][4] += A(ws) x B(xs), mma.sync
// K total = 7*32 = 224 (zero-padded n contributes 0). Acc fp32 exact.
// smem: xs 12544 + ws 6912 + mix 2688 = 22144 floats = 88576 B; 2 CTAs/SM.
// ---------------------------------------------------------------------------
#define XS_PITCH 392
#define WS_PITCH 36
#define MXT_XS   (32 * XS_PITCH)            // 12544
#define MXT_WS   (Hh * 32 * WS_PITCH)       // 6912
#define MXT_MIX  (CH * 96)                  // 2688
#define MXT_SMEM_BYTES ((MXT_XS + MXT_WS + MXT_MIX) * 4)

extern "C" __global__ void __launch_bounds__(384, 2)
mixer_kernel(const float* __restrict__ x, float* __restrict__ out) {
    extern __shared__ float sm[];
    uint32_t* xs_u  = (uint32_t*)sm;                     // [32][392] tf32 bits
    uint32_t* ws_u  = (uint32_t*)(sm + MXT_XS);          // [h][32][36] tf32 bits
    float*    mix_s = sm + MXT_XS + MXT_WS;              // [28][96]

    const int t    = threadIdx.x;
    const int b    = blockIdx.y;
    const int mt28 = blockIdx.x;          // 0..6
    const int lane = t & 31;
    const int warp = t >> 5;
    const int wh   = warp >> 1;           // h   0..5
    const int wm   = warp & 1;            // mtile 0..1

    float acc[8][4];
#pragma unroll
    for (int nt = 0; nt < 8; ++nt)
#pragma unroll
        for (int q = 0; q < 4; ++q) acc[nt][q] = 0.f;

    // zero pads once: xs rows 28-31 (full rows) and whole ws (covers n/m pads;
    // phase1 only ever writes nl<28, ml<28 so pads stay zero)
    for (int idx = t; idx < 4 * XS_PITCH; idx += 384) xs_u[28 * XS_PITCH + idx] = 0u;
    for (int idx = t; idx < MXT_WS; idx += 384) ws_u[idx] = 0u;

    for (int c = 0; c < NCH; ++c) {
        const int n0 = c * CH;
        __syncthreads();   // pads ready (c=0) / prior phase 2 done (c>0)
        // stage x chunk, tf32-rounded: 2688 float4
        {
            const float4* src = (const float4*)(x + ((size_t)b * Nn + n0) * DIMc);
#pragma unroll
            for (int i = 0; i < 7; ++i) {
                int idx = t + i * 384;
                int n = idx / 96, c4 = idx - n * 96;
                float4 v = src[idx];
                uint4 u = make_uint4(tf32r(v.x), tf32r(v.y), tf32r(v.z), tf32r(v.w));
                *(uint4*)&xs_u[n * XS_PITCH + c4 * 4] = u;
            }
        }
        // stage mix chunk: 672 float4
        {
            const float4* src = (const float4*)&g_mix[((size_t)b * Nn + n0) * 96];
            float4* dst = (float4*)mix_s;
            for (int idx = t; idx < 672; idx += 384) dst[idx] = src[idx];
        }
        __syncthreads();
        // phase 1 (scalar fp32): 784 (nl, ml) pairs
        for (int p = t; p < CH * TMX; p += 384) {
            int nl = p / TMX, ml = p - nl * TMX;
            int mg = mt28 * TMX + ml;
            const float4* wv = (const float4*)&g_wbt[((size_t)(n0 + nl) * Nn + mg) * Kk];
            float4 w0 = __ldg(wv + 0), w1 = __ldg(wv + 1);
            float4 w2 = __ldg(wv + 2), w3 = __ldg(wv + 3);
#pragma unroll
            for (int hh = 0; hh < Hh; ++hh) {
                const float4* mx = (const float4*)&mix_s[nl * 96 + hh * Kk];
                float4 m0 = mx[0], m1 = mx[1], m2 = mx[2], m3 = mx[3];
                float s = w0.x * m0.x;
                s = fmaf(w0.y, m0.y, s); s = fmaf(w0.z, m0.z, s); s = fmaf(w0.w, m0.w, s);
                s = fmaf(w1.x, m1.x, s); s = fmaf(w1.y, m1.y, s); s = fmaf(w1.z, m1.z, s); s = fmaf(w1.w, m1.w, s);
                s = fmaf(w2.x, m2.x, s); s = fmaf(w2.y, m2.y, s); s = fmaf(w2.z, m2.z, s); s = fmaf(w2.w, m2.w, s);
                s = fmaf(w3.x, m3.x, s); s = fmaf(w3.y, m3.y, s); s = fmaf(w3.z, m3.z, s); s = fmaf(w3.w, m3.w, s);
                ws_u[(hh * 32 + ml) * WS_PITCH + nl] = tf32r(s);
            }
        }
        __syncthreads();
        // phase 2: tensor. 4 ktiles of 8 within this chunk's 32 padded n.
#pragma unroll
        for (int kt = 0; kt < 4; ++kt) {
            int k8 = kt * 8;
            int arow = wm * 16 + (lane >> 2);
            int acol = k8 + (lane & 3);
            uint32_t a0 = ws_u[(wh * 32 + arow)     * WS_PITCH + acol];
            uint32_t a1 = ws_u[(wh * 32 + arow + 8) * WS_PITCH + acol];
            uint32_t a2 = ws_u[(wh * 32 + arow)     * WS_PITCH + acol + 4];
            uint32_t a3 = ws_u[(wh * 32 + arow + 8) * WS_PITCH + acol + 4];
            int base0 = (k8 + (lane & 3))     * XS_PITCH + wh * 64 + (lane >> 2);
            int base1 = (k8 + (lane & 3) + 4) * XS_PITCH + wh * 64 + (lane >> 2);
#pragma unroll
            for (int nt = 0; nt < 8; ++nt) {
                uint32_t b0 = xs_u[base0 + nt * 8];
                uint32_t b1 = xs_u[base1 + nt * 8];
                mma_tf32(acc[nt], a0, a1, a2, a3, b0, b1);
            }
        }
    }

    // epilogue: C-frag rows r, r+8; cols 2*(lane%4), +1 per ntile
    const int r    = lane >> 2;
    const int mlo  = mt28 * TMX + wm * 16 + r;        // always < 28 valid
    const int mhi  = mlo + 8;                          // wm=1: valid iff r<4
    const bool hi_ok = (wm == 0) || (r < 4);
    const int colb = wh * 64 + 2 * (lane & 3);
    float* ob = out + (size_t)b * Nn * DIMc;
#pragma unroll
    for (int nt = 0; nt < 8; ++nt) {
        int cc = colb + nt * 8;
        *(float2*)&ob[(size_t)mlo * DIMc + cc] = make_float2(acc[nt][0], acc[nt][1]);
        if (hi_ok)
            *(float2*)&ob[(size_t)mhi * DIMc + cc] = make_float2(acc[nt][2], acc[nt][3]);
    }
}

// ---------------------------------------------------------------------------
extern "C" void kernel_launch(void* const* d_in, const int* in_sizes, int n_in,
                              void* d_out, int out_size) {
    const float* x  = (const float*)d_in[0];
    const float* W1 = (const float*)d_in[1];
    const float* b1 = (const float*)d_in[2];
    const float* W2 = (const float*)d_in[3];
    const float* b2 = (const float*)d_in[4];
    const float* wb = (const float*)d_in[5];
    float* out = (float*)d_out;

    cudaFuncSetAttribute((const void*)adapter_kernel,
                         cudaFuncAttributeMaxDynamicSharedMemorySize,
                         AD_SMEM_FLOATS * 4);
    cudaFuncSetAttribute((const void*)mixer_kernel,
                         cudaFuncAttributeMaxDynamicSharedMemorySize,
                         MXT_SMEM_BYTES);

    transpose_wb_kernel<<<(Nn * Nn + 255) / 256, 256>>>(wb);
    adapter_kernel<<<392, 192, AD_SMEM_FLOATS * 4>>>(x, W1, b1, W2, b2);
    mixer_kernel<<<dim3(NCH, Bz), 384, MXT_SMEM_BYTES>>>(x, out);
}

// round 14
// speedup vs baseline: 1.6216x; 1.3110x over previous
#include <cuda_runtime.h>
#include <cstdint>

#define Bz   128
#define Nn   196
#define DIMc 384
#define Kk   16
#define Hh   6
#define TMX  28   // mixer m-tile width per CTA; 7*28 == 196
#define CH   28   // mixer n-chunk; 7*28 == 196
#define NCH  7

// Scratch (device globals — allocation-free)
__device__ __align__(16) float g_wbt[(size_t)Nn * Nn * Kk];      // [n][m][k]
__device__ __align__(16) float g_mix[(size_t)Bz * Nn * Hh * Kk]; // [b][n][h][k]

typedef unsigned long long ull;

__device__ __forceinline__ uint32_t tf32r(float f) {
    uint32_t u;
    asm("cvt.rna.tf32.f32 %0, %1;" : "=r"(u) : "f"(f));
    return u;
}
__device__ __forceinline__ void mma_tf32(float* c, uint32_t a0, uint32_t a1,
                                         uint32_t a2, uint32_t a3,
                                         uint32_t b0, uint32_t b1) {
    asm volatile(
        "mma.sync.aligned.m16n8k8.row.col.f32.tf32.tf32.f32 "
        "{%0,%1,%2,%3}, {%4,%5,%6,%7}, {%8,%9}, {%0,%1,%2,%3};"
        : "+f"(c[0]), "+f"(c[1]), "+f"(c[2]), "+f"(c[3])
        : "r"(a0), "r"(a1), "r"(a2), "r"(a3), "r"(b0), "r"(b1));
}

// ---------------------------------------------------------------------------
// Kernel 1: weight_bank [k][n][m] -> g_wbt [n][m][k]  (k contiguous)
// ---------------------------------------------------------------------------
extern "C" __global__ void transpose_wb_kernel(const float* __restrict__ wb) {
    int t = blockIdx.x * 256 + threadIdx.x;
    if (t >= Nn * Nn) return;
    int n = t / Nn, m = t % Nn;
    float v[Kk];
#pragma unroll
    for (int k = 0; k < Kk; ++k)
        v[k] = wb[((size_t)k * Nn + n) * Nn + m];   // coalesced over m
    float4* dst = (float4*)&g_wbt[(size_t)t * Kk];
    dst[0] = make_float4(v[0],  v[1],  v[2],  v[3]);
    dst[1] = make_float4(v[4],  v[5],  v[6],  v[7]);
    dst[2] = make_float4(v[8],  v[9],  v[10], v[11]);
    dst[3] = make_float4(v[12], v[13], v[14], v[15]);
}

// ---------------------------------------------------------------------------
// Kernel 2: adapter v5 (tensor, mma.sync tf32).
// 64 rows/CTA (392 CTAs, one wave @ 3 CTAs/SM), 128 threads = 4 warps.
// Warp w owns m-rows [16w,16w+16); 12 ntiles of 8 over N=96.
// GEMM1: K=384 in 4 chunks of 96 (As[64][100] tf32, Bs[96][104] tf32).
// GELU on acc -> H (tf32) into As; GEMM2 vs W2 (K=96); logits fp32 into As;
// per-(row,h) softmax over 16 k -> g_mix.
// smem = 64*100 + 96*104 floats = 16384 floats = 65536 B.
// ---------------------------------------------------------------------------
#define ATP_A 100
#define ATP_B 104
#define AT_SMEM_BYTES ((64 * ATP_A + 96 * ATP_B) * 4)

extern "C" __global__ void __launch_bounds__(128)
adapter_kernel(const float* __restrict__ x,
               const float* __restrict__ W1, const float* __restrict__ b1,
               const float* __restrict__ W2, const float* __restrict__ b2) {
    extern __shared__ float sm[];
    uint32_t* As = (uint32_t*)sm;                 // [64][100] tf32 bits / logits fp32
    uint32_t* Bs = (uint32_t*)(sm + 64 * ATP_A);  // [96][104] tf32 bits

    const int t    = threadIdx.x;
    const int lane = t & 31;
    const int warp = t >> 5;            // 0..3 -> m-rows 16w..16w+15
    const int row0 = blockIdx.x * 64;   // 392 CTAs

    const int qr = lane >> 2;           // 0..7
    const int qc = lane & 3;            // 0..3

    float acc[12][4];
#pragma unroll
    for (int nt = 0; nt < 12; ++nt)
#pragma unroll
        for (int q = 0; q < 4; ++q) acc[nt][q] = 0.f;

    // ---- GEMM1: 4 K-chunks of 96 ----
    for (int kc = 0; kc < 4; ++kc) {
        __syncthreads();
        // stage X chunk [64 rows][96 k] as tf32
        for (int idx = t; idx < 1536; idx += 128) {
            int r = idx / 24, c4 = idx - (idx / 24) * 24;
            float4 v = *(const float4*)&x[(size_t)(row0 + r) * DIMc + kc * 96 + c4 * 4];
            *(uint4*)&As[r * ATP_A + c4 * 4] =
                make_uint4(tf32r(v.x), tf32r(v.y), tf32r(v.z), tf32r(v.w));
        }
        // stage W1 chunk [96 k][96 n] as tf32
        for (int idx = t; idx < 2304; idx += 128) {
            int k = idx / 24, n4 = idx - (idx / 24) * 24;
            float4 v = *(const float4*)&W1[(size_t)(kc * 96 + k) * 96 + n4 * 4];
            *(uint4*)&Bs[k * ATP_B + n4 * 4] =
                make_uint4(tf32r(v.x), tf32r(v.y), tf32r(v.z), tf32r(v.w));
        }
        __syncthreads();
#pragma unroll
        for (int kt = 0; kt < 12; ++kt) {
            int k8 = kt * 8;
            int arow = warp * 16 + qr;
            uint32_t a0 = As[arow * ATP_A + k8 + qc];
            uint32_t a1 = As[(arow + 8) * ATP_A + k8 + qc];
            uint32_t a2 = As[arow * ATP_A + k8 + qc + 4];
            uint32_t a3 = As[(arow + 8) * ATP_A + k8 + qc + 4];
            int bb0 = (k8 + qc) * ATP_B + qr;
            int bb1 = (k8 + qc + 4) * ATP_B + qr;
#pragma unroll
            for (int nt = 0; nt < 12; ++nt) {
                uint32_t b0v = Bs[bb0 + nt * 8];
                uint32_t b1v = Bs[bb1 + nt * 8];
                mma_tf32(acc[nt], a0, a1, a2, a3, b0v, b1v);
            }
        }
    }
    __syncthreads();   // all warps done reading As/Bs

    // ---- GELU -> H (tf32) into As; stage W2 into Bs ----
    {
        int rlo = warp * 16 + qr, rhi = rlo + 8;
#pragma unroll
        for (int nt = 0; nt < 12; ++nt) {
            int c0 = nt * 8 + 2 * qc, c1 = c0 + 1;
            float g0 = acc[nt][0] + __ldg(&b1[c0]);
            float g1 = acc[nt][1] + __ldg(&b1[c1]);
            float g2 = acc[nt][2] + __ldg(&b1[c0]);
            float g3 = acc[nt][3] + __ldg(&b1[c1]);
            g0 = 0.5f * g0 * (1.0f + erff(g0 * 0.7071067811865476f));
            g1 = 0.5f * g1 * (1.0f + erff(g1 * 0.7071067811865476f));
            g2 = 0.5f * g2 * (1.0f + erff(g2 * 0.7071067811865476f));
            g3 = 0.5f * g3 * (1.0f + erff(g3 * 0.7071067811865476f));
            As[rlo * ATP_A + c0] = tf32r(g0);
            As[rlo * ATP_A + c1] = tf32r(g1);
            As[rhi * ATP_A + c0] = tf32r(g2);
            As[rhi * ATP_A + c1] = tf32r(g3);
        }
        for (int idx = t; idx < 2304; idx += 128) {
            int k = idx / 24, n4 = idx - (idx / 24) * 24;
            float4 v = *(const float4*)&W2[(size_t)k * 96 + n4 * 4];
            *(uint4*)&Bs[k * ATP_B + n4 * 4] =
                make_uint4(tf32r(v.x), tf32r(v.y), tf32r(v.z), tf32r(v.w));
        }
    }
    __syncthreads();

    // ---- GEMM2: K=96 ----
#pragma unroll
    for (int nt = 0; nt < 12; ++nt)
#pragma unroll
        for (int q = 0; q < 4; ++q) acc[nt][q] = 0.f;
#pragma unroll
    for (int kt = 0; kt < 12; ++kt) {
        int k8 = kt * 8;
        int arow = warp * 16 + qr;
        uint32_t a0 = As[arow * ATP_A + k8 + qc];
        uint32_t a1 = As[(arow + 8) * ATP_A + k8 + qc];
        uint32_t a2 = As[arow * ATP_A + k8 + qc + 4];
        uint32_t a3 = As[(arow + 8) * ATP_A + k8 + qc + 4];
        int bb0 = (k8 + qc) * ATP_B + qr;
        int bb1 = (k8 + qc + 4) * ATP_B + qr;
#pragma unroll
        for (int nt = 0; nt < 12; ++nt) {
            uint32_t b0v = Bs[bb0 + nt * 8];
            uint32_t b1v = Bs[bb1 + nt * 8];
            mma_tf32(acc[nt], a0, a1, a2, a3, b0v, b1v);
        }
    }
    __syncthreads();   // done reading As(H)

    // ---- logits (fp32) into As ----
    {
        float* Lf = (float*)As;
        int rlo = warp * 16 + qr, rhi = rlo + 8;
#pragma unroll
        for (int nt = 0; nt < 12; ++nt) {
            int c0 = nt * 8 + 2 * qc, c1 = c0 + 1;
            Lf[rlo * ATP_A + c0] = acc[nt][0] + __ldg(&b2[c0]);
            Lf[rlo * ATP_A + c1] = acc[nt][1] + __ldg(&b2[c1]);
            Lf[rhi * ATP_A + c0] = acc[nt][2] + __ldg(&b2[c0]);
            Lf[rhi * ATP_A + c1] = acc[nt][3] + __ldg(&b2[c1]);
        }
    }
    __syncthreads();

    // ---- softmax over k per (row, h): 384 tasks, 3 per thread ----
    {
        const float* Lf = (const float*)As;
        for (int task = t; task < 384; task += 128) {
            int r = task / 6, h = task - (task / 6) * 6;
            float vals[Kk];
            float vmax = -1e30f;
#pragma unroll
            for (int k = 0; k < Kk; ++k) {
                vals[k] = Lf[r * ATP_A + k * Hh + h];
                vmax = fmaxf(vmax, vals[k]);
            }
            float s = 0.f;
#pragma unroll
            for (int k = 0; k < Kk; ++k) { vals[k] = __expf(vals[k] - vmax); s += vals[k]; }
            float inv = 1.0f / s;
            float4* dst = (float4*)&g_mix[(size_t)(row0 + r) * 96 + h * Kk];
            dst[0] = make_float4(vals[0]  * inv, vals[1]  * inv, vals[2]  * inv, vals[3]  * inv);
            dst[1] = make_float4(vals[4]  * inv, vals[5]  * inv, vals[6]  * inv, vals[7]  * inv);
            dst[2] = make_float4(vals[8]  * inv, vals[9]  * inv, vals[10] * inv, vals[11] * inv);
            dst[3] = make_float4(vals[12] * inv, vals[13] * inv, vals[14] * inv, vals[15] * inv);
        }
    }
}

// ---------------------------------------------------------------------------
// Kernel 3: mixer v6 (R12, measured win). UNCHANGED.
// ---------------------------------------------------------------------------
#define XS_PITCH 392
#define WS_PITCH 36
#define MXT_XS   (32 * XS_PITCH)            // 12544
#define MXT_WS   (Hh * 32 * WS_PITCH)       // 6912
#define MXT_MIX  (CH * 96)                  // 2688
#define MXT_SMEM_BYTES ((MXT_XS + MXT_WS + MXT_MIX) * 4)

extern "C" __global__ void __launch_bounds__(384, 2)
mixer_kernel(const float* __restrict__ x, float* __restrict__ out) {
    extern __shared__ float sm[];
    uint32_t* xs_u  = (uint32_t*)sm;                     // [32][392] tf32 bits
    uint32_t* ws_u  = (uint32_t*)(sm + MXT_XS);          // [h][32][36] tf32 bits
    float*    mix_s = sm + MXT_XS + MXT_WS;              // [28][96]

    const int t    = threadIdx.x;
    const int b    = blockIdx.y;
    const int mt28 = blockIdx.x;          // 0..6
    const int lane = t & 31;
    const int warp = t >> 5;
    const int wh   = warp >> 1;           // h   0..5
    const int wm   = warp & 1;            // mtile 0..1

    float acc[8][4];
#pragma unroll
    for (int nt = 0; nt < 8; ++nt)
#pragma unroll
        for (int q = 0; q < 4; ++q) acc[nt][q] = 0.f;

    for (int idx = t; idx < 4 * XS_PITCH; idx += 384) xs_u[28 * XS_PITCH + idx] = 0u;
    for (int idx = t; idx < MXT_WS; idx += 384) ws_u[idx] = 0u;

    for (int c = 0; c < NCH; ++c) {
        const int n0 = c * CH;
        __syncthreads();
        {
            const float4* src = (const float4*)(x + ((size_t)b * Nn + n0) * DIMc);
#pragma unroll
            for (int i = 0; i < 7; ++i) {
                int idx = t + i * 384;
                int n = idx / 96, c4 = idx - n * 96;
                float4 v = src[idx];
                uint4 u = make_uint4(tf32r(v.x), tf32r(v.y), tf32r(v.z), tf32r(v.w));
                *(uint4*)&xs_u[n * XS_PITCH + c4 * 4] = u;
            }
        }
        {
            const float4* src = (const float4*)&g_mix[((size_t)b * Nn + n0) * 96];
            float4* dst = (float4*)mix_s;
            for (int idx = t; idx < 672; idx += 384) dst[idx] = src[idx];
        }
        __syncthreads();
        for (int p = t; p < CH * TMX; p += 384) {
            int nl = p / TMX, ml = p - nl * TMX;
            int mg = mt28 * TMX + ml;
            const float4* wv = (const float4*)&g_wbt[((size_t)(n0 + nl) * Nn + mg) * Kk];
            float4 w0 = __ldg(wv + 0), w1 = __ldg(wv + 1);
            float4 w2 = __ldg(wv + 2), w3 = __ldg(wv + 3);
#pragma unroll
            for (int hh = 0; hh < Hh; ++hh) {
                const float4* mx = (const float4*)&mix_s[nl * 96 + hh * Kk];
                float4 m0 = mx[0], m1 = mx[1], m2 = mx[2], m3 = mx[3];
                float s = w0.x * m0.x;
                s = fmaf(w0.y, m0.y, s); s = fmaf(w0.z, m0.z, s); s = fmaf(w0.w, m0.w, s);
                s = fmaf(w1.x, m1.x, s); s = fmaf(w1.y, m1.y, s); s = fmaf(w1.z, m1.z, s); s = fmaf(w1.w, m1.w, s);
                s = fmaf(w2.x, m2.x, s); s = fmaf(w2.y, m2.y, s); s = fmaf(w2.z, m2.z, s); s = fmaf(w2.w, m2.w, s);
                s = fmaf(w3.x, m3.x, s); s = fmaf(w3.y, m3.y, s); s = fmaf(w3.z, m3.z, s); s = fmaf(w3.w, m3.w, s);
                ws_u[(hh * 32 + ml) * WS_PITCH + nl] = tf32r(s);
            }
        }
        __syncthreads();
#pragma unroll
        for (int kt = 0; kt < 4; ++kt) {
            int k8 = kt * 8;
            int arow = wm * 16 + (lane >> 2);
            int acol = k8 + (lane & 3);
            uint32_t a0 = ws_u[(wh * 32 + arow)     * WS_PITCH + acol];
            uint32_t a1 = ws_u[(wh * 32 + arow + 8) * WS_PITCH + acol];
            uint32_t a2 = ws_u[(wh * 32 + arow)     * WS_PITCH + acol + 4];
            uint32_t a3 = ws_u[(wh * 32 + arow + 8) * WS_PITCH + acol + 4];
            int base0 = (k8 + (lane & 3))     * XS_PITCH + wh * 64 + (lane >> 2);
            int base1 = (k8 + (lane & 3) + 4) * XS_PITCH + wh * 64 + (lane >> 2);
#pragma unroll
            for (int nt = 0; nt < 8; ++nt) {
                uint32_t b0 = xs_u[base0 + nt * 8];
                uint32_t b1 = xs_u[base1 + nt * 8];
                mma_tf32(acc[nt], a0, a1, a2, a3, b0, b1);
            }
        }
    }

    const int r    = lane >> 2;
    const int mlo  = mt28 * TMX + wm * 16 + r;
    const int mhi  = mlo + 8;
    const bool hi_ok = (wm == 0) || (r < 4);
    const int colb = wh * 64 + 2 * (lane & 3);
    float* ob = out + (size_t)b * Nn * DIMc;
#pragma unroll
    for (int nt = 0; nt < 8; ++nt) {
        int cc = colb + nt * 8;
        *(float2*)&ob[(size_t)mlo * DIMc + cc] = make_float2(acc[nt][0], acc[nt][1]);
        if (hi_ok)
            *(float2*)&ob[(size_t)mhi * DIMc + cc] = make_float2(acc[nt][2], acc[nt][3]);
    }
}

// ---------------------------------------------------------------------------
extern "C" void kernel_launch(void* const* d_in, const int* in_sizes, int n_in,
                              void* d_out, int out_size) {
    const float* x  = (const float*)d_in[0];
    const float* W1 = (const float*)d_in[1];
    const float* b1 = (const float*)d_in[2];
    const float* W2 = (const float*)d_in[3];
    const float* b2 = (const float*)d_in[4];
    const float* wb = (const float*)d_in[5];
    float* out = (float*)d_out;

    cudaFuncSetAttribute((const void*)adapter_kernel,
                         cudaFuncAttributeMaxDynamicSharedMemorySize,
                         AT_SMEM_BYTES);
    cudaFuncSetAttribute((const void*)mixer_kernel,
                         cudaFuncAttributeMaxDynamicSharedMemorySize,
                         MXT_SMEM_BYTES);

    transpose_wb_kernel<<<(Nn * Nn + 255) / 256, 256>>>(wb);
    adapter_kernel<<<392, 128, AT_SMEM_BYTES>>>(x, W1, b1, W2, b2);
    mixer_kernel<<<dim3(NCH, Bz), 384, MXT_SMEM_BYTES>>>(x, out);
}